// round 5
// baseline (speedup 1.0000x reference)
#include <cuda_runtime.h>
#include <cstdint>

// ============================================================================
// StandardSelfAttention, TF32 mma.sync:
//  - GEMMs: 128x128x32 double-buffered smem pipeline (1 sync / ktile).
//  - Attention: BQ=128, 4 warps x 32 q-rows (2 m-tiles/warp), permuted Q/K
//    smem for uint2 fragment loads, P reformat via shuffles (no P smem),
//    fully-masked-warp skip, big blocks launched first.
//  - cudaFuncSetAttribute done once at first launch (outside graph capture).
// ============================================================================

#define D_MODEL 1024
#define N_HEADS 16
#define D_HEAD 64
#define SEQ 2048
#define BATCH 2
#define M_ROWS (BATCH * SEQ)
#define BH (BATCH * N_HEADS)

__device__ float g_Q[BH * SEQ * D_HEAD];
__device__ float g_K[BH * SEQ * D_HEAD];
__device__ float g_V[BH * SEQ * D_HEAD];
__device__ float g_ctx[M_ROWS * D_MODEL];

__device__ __forceinline__ uint32_t f2tf(float x) {
    uint32_t r;
    asm("cvt.rna.tf32.f32 %0, %1;" : "=r"(r) : "f"(x));
    return r;
}

__device__ __forceinline__ void mma_tf32(float* c,
    uint32_t a0, uint32_t a1, uint32_t a2, uint32_t a3,
    uint32_t b0, uint32_t b1)
{
    asm volatile(
        "mma.sync.aligned.m16n8k8.row.col.f32.tf32.tf32.f32 "
        "{%0,%1,%2,%3}, {%4,%5,%6,%7}, {%8,%9}, {%0,%1,%2,%3};\n"
        : "+f"(c[0]), "+f"(c[1]), "+f"(c[2]), "+f"(c[3])
        : "r"(a0), "r"(a1), "r"(a2), "r"(a3), "r"(b0), "r"(b1));
}

// ----------------------------------------------------------------------------
// TF32 GEMM, double-buffered. C = A[M,1024] @ W[1024,1024] + bias
// mode 0: head-split tf32-rounded output [b,h,s,dh] (scale folded)
// mode 1: plain [m,n] fp32
// ----------------------------------------------------------------------------
constexpr int GAST = 36;
constexpr int GBST = 136;
constexpr int GEMM_SMEM = (2 * 128 * GAST + 2 * 32 * GBST) * 4;  // 71680 B

__global__ __launch_bounds__(256) void gemm_tf32(
    const float* __restrict__ A, const float* __restrict__ W,
    const float* __restrict__ bias, float* __restrict__ C,
    int mode, float scale)
{
    extern __shared__ uint32_t gsm[];
    uint32_t* Asm = gsm;                       // [2][128][GAST]
    uint32_t* Bsm = gsm + 2 * 128 * GAST;      // [2][32][GBST]

    int tid = threadIdx.x;
    int lane = tid & 31, wid = tid >> 5;
    int wm = wid >> 2, wn = wid & 3;
    int bm = blockIdx.y * 128, bn = blockIdx.x * 128;
    int r = lane >> 2, cc4 = lane & 3;

    int arow = tid >> 1;
    int acol = (tid & 1) * 16;
    int brow = tid >> 3;
    int bcol = (tid & 7) * 4;

    const float* Ap = A + (size_t)(bm + arow) * 1024 + acol;
    const float* Wp = W + (size_t)brow * 1024 + bn + bcol;

    float acc[4][4][4] = {};

    float4 areg[4], breg[4];
    #pragma unroll
    for (int i = 0; i < 4; i++) {
        areg[i] = *(const float4*)(Ap + i * 4);
        breg[i] = *(const float4*)(Wp + (size_t)i * 32);
    }
    // store stage 0
    {
        uint32_t* as = Asm;
        uint32_t* bs = Bsm;
        #pragma unroll
        for (int i = 0; i < 4; i++) {
            uint32_t* d = &as[arow * GAST + acol + i * 4];
            d[0] = f2tf(areg[i].x); d[1] = f2tf(areg[i].y);
            d[2] = f2tf(areg[i].z); d[3] = f2tf(areg[i].w);
            uint32_t* e = &bs[brow * GBST + bcol + i * 32];
            e[0] = f2tf(breg[i].x); e[1] = f2tf(breg[i].y);
            e[2] = f2tf(breg[i].z); e[3] = f2tf(breg[i].w);
        }
    }
    __syncthreads();

    for (int kt = 0; kt < 32; kt++) {
        int cur = kt & 1;
        bool has_next = (kt + 1) < 32;
        // prefetch next tile into regs (latency hidden by compute below)
        if (has_next) {
            int k0n = (kt + 1) * 32;
            #pragma unroll
            for (int i = 0; i < 4; i++) {
                areg[i] = *(const float4*)(Ap + k0n + i * 4);
                breg[i] = *(const float4*)(Wp + (size_t)k0n * 1024 + (size_t)i * 32);
            }
        }

        const uint32_t* as = Asm + cur * 128 * GAST;
        const uint32_t* bs = Bsm + cur * 32 * GBST;
        #pragma unroll
        for (int ks = 0; ks < 4; ks++) {
            int k = ks * 8;
            uint32_t af[4][4];
            #pragma unroll
            for (int mt = 0; mt < 4; mt++) {
                const uint32_t* ab = &as[(wm * 64 + mt * 16 + r) * GAST + k + cc4];
                af[mt][0] = ab[0];
                af[mt][1] = ab[8 * GAST];
                af[mt][2] = ab[4];
                af[mt][3] = ab[8 * GAST + 4];
            }
            #pragma unroll
            for (int nt = 0; nt < 4; nt++) {
                const uint32_t* bb = &bs[(k + cc4) * GBST + wn * 32 + nt * 8 + r];
                uint32_t b0 = bb[0], b1 = bb[4 * GBST];
                #pragma unroll
                for (int mt = 0; mt < 4; mt++)
                    mma_tf32(acc[mt][nt], af[mt][0], af[mt][1], af[mt][2], af[mt][3], b0, b1);
            }
        }

        if (has_next) {
            uint32_t* asn = Asm + (cur ^ 1) * 128 * GAST;
            uint32_t* bsn = Bsm + (cur ^ 1) * 32 * GBST;
            #pragma unroll
            for (int i = 0; i < 4; i++) {
                uint32_t* d = &asn[arow * GAST + acol + i * 4];
                d[0] = f2tf(areg[i].x); d[1] = f2tf(areg[i].y);
                d[2] = f2tf(areg[i].z); d[3] = f2tf(areg[i].w);
                uint32_t* e = &bsn[brow * GBST + bcol + i * 32];
                e[0] = f2tf(breg[i].x); e[1] = f2tf(breg[i].y);
                e[2] = f2tf(breg[i].z); e[3] = f2tf(breg[i].w);
            }
        }
        __syncthreads();
    }

    #pragma unroll
    for (int mt = 0; mt < 4; mt++) {
        int r0 = bm + wm * 64 + mt * 16 + r;
        #pragma unroll
        for (int nt = 0; nt < 4; nt++) {
            int col = bn + wn * 32 + nt * 8 + 2 * cc4;
            float bz0 = bias[col], bz1 = bias[col + 1];
            #pragma unroll
            for (int half = 0; half < 2; half++) {
                int m = r0 + half * 8;
                float v0 = acc[mt][nt][half * 2 + 0] + bz0;
                float v1 = acc[mt][nt][half * 2 + 1] + bz1;
                if (mode == 0) {
                    v0 = __uint_as_float(f2tf(v0 * scale));
                    v1 = __uint_as_float(f2tf(v1 * scale));
                    int b = m >> 11, s = m & 2047;
                    int h = col >> 6, dh = col & 63;
                    *(float2*)&C[(((size_t)(b * N_HEADS + h)) * SEQ + s) * D_HEAD + dh] =
                        make_float2(v0, v1);
                } else {
                    *(float2*)&C[(size_t)m * 1024 + col] = make_float2(v0, v1);
                }
            }
        }
    }
}

// ----------------------------------------------------------------------------
// Flash attention. BQ=128 q-rows/CTA, 4 warps x (2 m-tiles of 16 rows).
// Q/K smem permuted within 8-col groups so (c, c+4) frag pair = one uint2.
// V plain [key][d]. P built from S-accumulators via shuffles.
// ----------------------------------------------------------------------------
constexpr int ST = 72;                                    // word stride
constexpr int ATTN_SMEM = (128 + 64 + 64) * ST * 4;       // 73728 B

__global__ __launch_bounds__(128) void attn_mma(
    const float* __restrict__ Q, const float* __restrict__ K,
    const float* __restrict__ V, const float* __restrict__ pb,
    float* __restrict__ ctx)
{
    extern __shared__ uint32_t sm[];
    uint32_t* Qs = sm;              // [128][ST] d-permuted
    uint32_t* Ks = Qs + 128 * ST;   // [64][ST]  d-permuted
    uint32_t* Vs = Ks + 64 * ST;    // [64][ST]  plain [key][d]

    int tid = threadIdx.x, lane = tid & 31, w = tid >> 5;
    int r = lane >> 2, c = lane & 3;
    int bh = blockIdx.y, b = bh >> 4, h = bh & 15;
    int qb = gridDim.x - 1 - blockIdx.x;     // big blocks first
    int q0 = qb * 128;

    // Load Q tile once, permuted: perm(4*c4+t) = (c4>>1)*8 + (c4&1) + 2t
    const float* Qg = Q + ((size_t)bh * SEQ + q0) * D_HEAD;
    for (int i = tid; i < 128 * 16; i += 128) {
        int rr = i >> 4, c4 = i & 15;
        float4 v = *(const float4*)(Qg + (size_t)rr * D_HEAD + c4 * 4);
        uint32_t* d = &Qs[rr * ST + (c4 >> 1) * 8 + (c4 & 1)];
        d[0] = __float_as_uint(v.x);
        d[2] = __float_as_uint(v.y);
        d[4] = __float_as_uint(v.z);
        d[6] = __float_as_uint(v.w);
    }

    float oacc[2][8][4] = {};
    float mrow[2][2] = {{-1e30f, -1e30f}, {-1e30f, -1e30f}};
    float lrow[2][2] = {{0.f, 0.f}, {0.f, 0.f}};

    const float* Kg = K + (size_t)bh * SEQ * D_HEAD;
    const float* Vg = V + (size_t)bh * SEQ * D_HEAD;
    const float* pbase = pb + (size_t)h * SEQ * SEQ;
    int wrow = q0 + w * 32;                 // warp's first q row
    int srcA = (lane & ~3) | ((lane >> 1) & 1);   // r*4 + (c>>1)
    int srcB = srcA + 2;
    bool odd = (lane & 1);

    for (int k0 = 0; k0 < q0 + 128; k0 += 64) {
        __syncthreads();
        for (int i = tid; i < 64 * 16; i += 128) {
            int rr = i >> 4, c4 = i & 15;
            float4 kv = *(const float4*)(Kg + (size_t)(k0 + rr) * D_HEAD + c4 * 4);
            uint32_t* dk = &Ks[rr * ST + (c4 >> 1) * 8 + (c4 & 1)];
            dk[0] = __float_as_uint(kv.x);
            dk[2] = __float_as_uint(kv.y);
            dk[4] = __float_as_uint(kv.z);
            dk[6] = __float_as_uint(kv.w);
            float4 vv = *(const float4*)(Vg + (size_t)(k0 + rr) * D_HEAD + c4 * 4);
            *(float4*)((float*)&Vs[rr * ST + c4 * 4]) = vv;
        }
        __syncthreads();

        if (k0 > wrow + 31) continue;       // this warp fully masked for tile

        // ---- S = Q @ K^T (scale pre-folded into Q) ----
        float sacc[2][8][4] = {};
        #pragma unroll
        for (int ks = 0; ks < 8; ks++) {
            uint2 qa[2], qc[2];
            #pragma unroll
            for (int mt = 0; mt < 2; mt++) {
                int row = w * 32 + mt * 16;
                qa[mt] = *(const uint2*)&Qs[(row + r) * ST + ks * 8 + 2 * c];       // a0,a2
                qc[mt] = *(const uint2*)&Qs[(row + 8 + r) * ST + ks * 8 + 2 * c];   // a1,a3
            }
            #pragma unroll
            for (int nt = 0; nt < 8; nt++) {
                uint2 kb = *(const uint2*)&Ks[(nt * 8 + r) * ST + ks * 8 + 2 * c];  // b0,b1
                #pragma unroll
                for (int mt = 0; mt < 2; mt++)
                    mma_tf32(sacc[mt][nt], qa[mt].x, qc[mt].x, qa[mt].y, qc[mt].y,
                             kb.x, kb.y);
            }
        }

        // ---- bias + causal mask + streaming softmax (per m-tile) ----
        #pragma unroll
        for (int mt = 0; mt < 2; mt++) {
            int row0 = wrow + mt * 16 + r;
            bool needm = (k0 + 63 > wrow + mt * 16);
            #pragma unroll
            for (int nt = 0; nt < 8; nt++) {
                int col = k0 + nt * 8 + 2 * c;
                float2 bz0 = *(const float2*)(pbase + (size_t)row0 * SEQ + col);
                float2 bz1 = *(const float2*)(pbase + (size_t)(row0 + 8) * SEQ + col);
                sacc[mt][nt][0] += bz0.x; sacc[mt][nt][1] += bz0.y;
                sacc[mt][nt][2] += bz1.x; sacc[mt][nt][3] += bz1.y;
                if (needm) {
                    if (col > row0)         sacc[mt][nt][0] = -1e30f;
                    if (col + 1 > row0)     sacc[mt][nt][1] = -1e30f;
                    if (col > row0 + 8)     sacc[mt][nt][2] = -1e30f;
                    if (col + 1 > row0 + 8) sacc[mt][nt][3] = -1e30f;
                }
            }

            float t0 = -1e30f, t1 = -1e30f;
            #pragma unroll
            for (int nt = 0; nt < 8; nt++) {
                t0 = fmaxf(t0, fmaxf(sacc[mt][nt][0], sacc[mt][nt][1]));
                t1 = fmaxf(t1, fmaxf(sacc[mt][nt][2], sacc[mt][nt][3]));
            }
            t0 = fmaxf(t0, __shfl_xor_sync(0xffffffffu, t0, 1));
            t0 = fmaxf(t0, __shfl_xor_sync(0xffffffffu, t0, 2));
            t1 = fmaxf(t1, __shfl_xor_sync(0xffffffffu, t1, 1));
            t1 = fmaxf(t1, __shfl_xor_sync(0xffffffffu, t1, 2));

            float mn0 = fmaxf(mrow[mt][0], t0), mn1 = fmaxf(mrow[mt][1], t1);
            float cor0 = __expf(mrow[mt][0] - mn0), cor1 = __expf(mrow[mt][1] - mn1);
            mrow[mt][0] = mn0; mrow[mt][1] = mn1;
            lrow[mt][0] *= cor0; lrow[mt][1] *= cor1;

            float ps0 = 0.f, ps1 = 0.f;
            #pragma unroll
            for (int nt = 0; nt < 8; nt++) {
                float p00 = __expf(sacc[mt][nt][0] - mn0);
                float p01 = __expf(sacc[mt][nt][1] - mn0);
                float p10 = __expf(sacc[mt][nt][2] - mn1);
                float p11 = __expf(sacc[mt][nt][3] - mn1);
                ps0 += p00 + p01; ps1 += p10 + p11;
                sacc[mt][nt][0] = __uint_as_float(f2tf(p00));
                sacc[mt][nt][1] = __uint_as_float(f2tf(p01));
                sacc[mt][nt][2] = __uint_as_float(f2tf(p10));
                sacc[mt][nt][3] = __uint_as_float(f2tf(p11));
            }
            ps0 += __shfl_xor_sync(0xffffffffu, ps0, 1);
            ps0 += __shfl_xor_sync(0xffffffffu, ps0, 2);
            ps1 += __shfl_xor_sync(0xffffffffu, ps1, 1);
            ps1 += __shfl_xor_sync(0xffffffffu, ps1, 2);
            lrow[mt][0] += ps0; lrow[mt][1] += ps1;

            #pragma unroll
            for (int nt = 0; nt < 8; nt++) {
                oacc[mt][nt][0] *= cor0; oacc[mt][nt][1] *= cor0;
                oacc[mt][nt][2] *= cor1; oacc[mt][nt][3] *= cor1;
            }
        }

        // ---- O += P @ V : P fragments via shuffle from S accumulators ----
        #pragma unroll
        for (int ks = 0; ks < 8; ks++) {
            uint32_t pa[2][4];
            #pragma unroll
            for (int mt = 0; mt < 2; mt++) {
                float s0 = sacc[mt][ks][0], s1 = sacc[mt][ks][1];
                float s2 = sacc[mt][ks][2], s3 = sacc[mt][ks][3];
                float v00 = __shfl_sync(0xffffffffu, s0, srcA);
                float v01 = __shfl_sync(0xffffffffu, s1, srcA);
                float v10 = __shfl_sync(0xffffffffu, s0, srcB);
                float v11 = __shfl_sync(0xffffffffu, s1, srcB);
                float w00 = __shfl_sync(0xffffffffu, s2, srcA);
                float w01 = __shfl_sync(0xffffffffu, s3, srcA);
                float w10 = __shfl_sync(0xffffffffu, s2, srcB);
                float w11 = __shfl_sync(0xffffffffu, s3, srcB);
                pa[mt][0] = __float_as_uint(odd ? v01 : v00);  // P[r][kk+c]
                pa[mt][1] = __float_as_uint(odd ? w01 : w00);  // P[r+8][kk+c]
                pa[mt][2] = __float_as_uint(odd ? v11 : v10);  // P[r][kk+c+4]
                pa[mt][3] = __float_as_uint(odd ? w11 : w10);  // P[r+8][kk+c+4]
            }
            #pragma unroll
            for (int nt = 0; nt < 8; nt++) {
                uint32_t b0 = Vs[(ks * 8 + c) * ST + nt * 8 + r];
                uint32_t b1 = Vs[(ks * 8 + c + 4) * ST + nt * 8 + r];
                #pragma unroll
                for (int mt = 0; mt < 2; mt++)
                    mma_tf32(oacc[mt][nt], pa[mt][0], pa[mt][1], pa[mt][2], pa[mt][3],
                             b0, b1);
            }
        }
    }

    // epilogue
    #pragma unroll
    for (int mt = 0; mt < 2; mt++) {
        int row0 = wrow + mt * 16 + r;
        float inv0 = 1.0f / lrow[mt][0], inv1 = 1.0f / lrow[mt][1];
        float* cb = ctx + ((size_t)(b * SEQ + row0)) * D_MODEL + h * D_HEAD;
        #pragma unroll
        for (int nt = 0; nt < 8; nt++) {
            *(float2*)(cb + nt * 8 + 2 * c) =
                make_float2(oacc[mt][nt][0] * inv0, oacc[mt][nt][1] * inv0);
            *(float2*)(cb + (size_t)8 * D_MODEL + nt * 8 + 2 * c) =
                make_float2(oacc[mt][nt][2] * inv1, oacc[mt][nt][3] * inv1);
        }
    }
}

// ----------------------------------------------------------------------------
// Launch. Inputs: 0:x 1:mask 2:Wq 3:bq 4:Wk 5:bk 6:Wv 7:bv 8:Wo 9:bo 10:pos_bias
// ----------------------------------------------------------------------------
extern "C" void kernel_launch(void* const* d_in, const int* in_sizes, int n_in,
                              void* d_out, int out_size)
{
    const float* x  = (const float*)d_in[0];
    const float* Wq = (const float*)d_in[2];
    const float* bq = (const float*)d_in[3];
    const float* Wk = (const float*)d_in[4];
    const float* bk = (const float*)d_in[5];
    const float* Wv = (const float*)d_in[6];
    const float* bv = (const float*)d_in[7];
    const float* Wo = (const float*)d_in[8];
    const float* bo = (const float*)d_in[9];
    const float* pb = (const float*)d_in[10];
    float* out = (float*)d_out;

    float *qp, *kp, *vp, *cp;
    cudaGetSymbolAddress((void**)&qp, g_Q);
    cudaGetSymbolAddress((void**)&kp, g_K);
    cudaGetSymbolAddress((void**)&vp, g_V);
    cudaGetSymbolAddress((void**)&cp, g_ctx);

    // One-time attribute setup: runs on the first (correctness) call, never
    // during graph capture. Work done per call is identical either way.
    static const int _attrs_once = []() {
        cudaFuncSetAttribute(gemm_tf32,
            cudaFuncAttributeMaxDynamicSharedMemorySize, GEMM_SMEM);
        cudaFuncSetAttribute(attn_mma,
            cudaFuncAttributeMaxDynamicSharedMemorySize, ATTN_SMEM);
        return 0;
    }();
    (void)_attrs_once;

    dim3 ggrid(8, 32);
    gemm_tf32<<<ggrid, 256, GEMM_SMEM>>>(x, Wq, bq, qp, 0, 0.125f);
    gemm_tf32<<<ggrid, 256, GEMM_SMEM>>>(x, Wk, bk, kp, 0, 1.0f);
    gemm_tf32<<<ggrid, 256, GEMM_SMEM>>>(x, Wv, bv, vp, 0, 1.0f);

    dim3 agrid(SEQ / 128, BH);   // (16, 32)
    attn_mma<<<agrid, 128, ATTN_SMEM>>>(qp, kp, vp, pb, cp);

    gemm_tf32<<<ggrid, 256, GEMM_SMEM>>>(cp, Wo, bo, out, 1, 1.0f);
}